// round 10
// baseline (speedup 1.0000x reference)
#include <cuda_runtime.h>
#include <math.h>
#include <stdint.h>
#include <cstdint>

#define NBULK        62
#define DDIM         64
#define NBATCH       8192
#define LOGZ_BLOCKS  16
#define PSI_BLOCKS   256
#define TOTAL_BLOCKS (LOGZ_BLOCKS + PSI_BLOCKS)
#define NTHREADS     256
#define MBLK         32

// ---------------- psi-block shared memory layout (float offsets) -------------
#define ENV_STRIDE 68
#define SM_ENV     0                        // 32*68 = 2176 (env[m][k])
#define SM_RIGHT   2176                     // 128 floats
#define SM_RED     2304                     // 128 floats ([4 nq][32 m])
#define SM_CFG     2432                     // 512 floats = 2048 B (cfgS[site][m])
#define SM_B       2944                     // byte 11776 (128B aligned); 16384 floats (hi|lo)
#define SM_TOTALF  (2944 + 16384)           // 19328 floats = 77312 bytes -> 2 blocks/SM

// ---------------- logz-block shared memory layout (fits inside psi size) -----
#define LZ_ENV  0
#define LZ_A    4160
#define LZ_TMP  (LZ_A + 8192)
#define LZ_RED  (LZ_TMP + 576)

// ---------------- global scratch (zero-initialized at load) ------------------
__device__ float    g_bulkT[(size_t)NBULK * 16384];   // per site: Bhi frag-order[8192] | Blo[8192]
__device__ float    g_envbuf[2][DDIM * DDIM];
__device__ float    g_maxarr[2][LOGZ_BLOCKS];
__device__ float    g_blocksums[PSI_BLOCKS];
__device__ float    g_logz;
__device__ unsigned g_bar_count;
__device__ volatile unsigned g_bar_gen;
__device__ unsigned g_done;
__device__ unsigned g_fin;

__device__ __forceinline__ void cp16(unsigned dst, const void* src) {
    asm volatile("cp.async.cg.shared.global [%0], [%1], 16;" :: "r"(dst), "l"(src) : "memory");
}
__device__ __forceinline__ void cp_commit() { asm volatile("cp.async.commit_group;" ::: "memory"); }
__device__ __forceinline__ void cp_wait0()  { asm volatile("cp.async.wait_group 0;" ::: "memory"); }

// m16n8k8 tf32 MMA, f32 accumulate in-place
__device__ __forceinline__ void mma8(float& d0, float& d1, float& d2, float& d3,
                                     unsigned a0, unsigned a1, unsigned a2, unsigned a3,
                                     unsigned b0, unsigned b1) {
    asm volatile("mma.sync.aligned.m16n8k8.row.col.f32.tf32.tf32.f32 "
                 "{%0,%1,%2,%3}, {%4,%5,%6,%7}, {%8,%9}, {%0,%1,%2,%3};"
                 : "+f"(d0), "+f"(d1), "+f"(d2), "+f"(d3)
                 : "r"(a0), "r"(a1), "r"(a2), "r"(a3), "r"(b0), "r"(b1));
}

__device__ __forceinline__ void gbar_arrive_spin(unsigned target) {
    __threadfence();
    unsigned t = atomicAdd(&g_bar_count, 1u);
    if (t == LOGZ_BLOCKS - 1) {
        g_bar_count = 0;
        __threadfence();
        g_bar_gen = target;
    } else {
        while (g_bar_gen < target) { }
    }
}

// ============ pre-pass: bulk -> tf32 hi/lo in B-fragment order ===============
__global__ void pre_kernel(const float* __restrict__ bulk) {
    const int t = blockIdx.x;
    const float* src = bulk + (size_t)t * 8192;   // [k][n], n = p*64+j
    float* dst = g_bulkT + (size_t)t * 16384;
    for (int idx = threadIdx.x; idx < 8192; idx += blockDim.x) {
        int k = idx >> 7, n = idx & 127;
        float v = src[idx];
        unsigned hb = __float_as_uint(v) & 0xFFFFE000u;
        float lof = v - __uint_as_float(hb);
        unsigned lb = __float_as_uint(lof) & 0xFFFFE000u;
        int kt   = k >> 3;
        int lane = ((n & 7) << 2) | (k & 3);
        int b    = (k >> 2) & 1;
        int ntp  = n >> 4;
        int q    = (((n >> 3) & 1) << 1) | b;
        int off  = kt * 1024 + ntp * 128 + lane * 4 + q;
        dst[off]        = __uint_as_float(hb);
        dst[8192 + off] = __uint_as_float(lb);
    }
}

__global__ __launch_bounds__(NTHREADS, 2)
void main_kernel(const int* __restrict__ cfg,
                 const float* __restrict__ left,
                 const float* __restrict__ bulk,
                 const float* __restrict__ right,
                 float* __restrict__ out) {
    extern __shared__ float smem[];
    const int tid = threadIdx.x;

    if (blockIdx.x < LOGZ_BLOCKS) {
        // ==================== log-Z path: 16 cooperating blocks (unchanged) =====
        unsigned genl = 0;
        const int jb = blockIdx.x << 2;
        unsigned* maxw = (unsigned*)(smem + LZ_RED);

        if (blockIdx.x == 0) {
            for (int idx = tid; idx < DDIM * DDIM; idx += NTHREADS) {
                int i = idx >> 6, j = idx & 63;
                g_envbuf[0][idx] = left[i] * left[j] + left[64 + i] * left[64 + j];
            }
        }
        __syncthreads();
        if (tid == 0) gbar_arrive_spin(++genl);
        __syncthreads();
        __threadfence();

        float inv_scale = 1.0f, log_scale = 0.0f;

        for (int t = 0; t < NBULK; t++) {
            const int cur = t & 1, nxt = cur ^ 1;
            if (tid == 0) *maxw = 0u;
            const float4* asrc = (const float4*)(bulk + (size_t)t * 8192);
            float4* adst = (float4*)(smem + LZ_A);
#pragma unroll
            for (int i = 0; i < 8; i++) adst[tid + (i << 8)] = asrc[tid + (i << 8)];
            for (int idx = tid; idx < DDIM * DDIM; idx += NTHREADS) {
                int d = idx >> 6, e = idx & 63;
                smem[LZ_ENV + d * 65 + e] = __ldcg(&g_envbuf[cur][idx]) * inv_scale;
            }
            __syncthreads();

            const int d  = tid & 63;
            const int jj = tid >> 6;
            float t0 = 0.0f, t1 = 0.0f;
#pragma unroll 8
            for (int e = 0; e < 64; e++) {
                float ev = smem[LZ_ENV + d * 65 + e];
                t0 = fmaf(ev, smem[LZ_A + e * 128 + jb + jj], t0);
                t1 = fmaf(ev, smem[LZ_A + e * 128 + 64 + jb + jj], t1);
            }
            smem[LZ_TMP + d * 9 + jj]     = t0;
            smem[LZ_TMP + d * 9 + 4 + jj] = t1;
            __syncthreads();

            float o = 0.0f;
#pragma unroll 8
            for (int dd = 0; dd < 64; dd++) {
                o = fmaf(smem[LZ_A + dd * 128 + d],      smem[LZ_TMP + dd * 9 + jj],     o);
                o = fmaf(smem[LZ_A + dd * 128 + 64 + d], smem[LZ_TMP + dd * 9 + 4 + jj], o);
            }
            g_envbuf[nxt][d * 64 + jb + jj] = o;

            float am = fabsf(o);
#pragma unroll
            for (int off = 16; off > 0; off >>= 1)
                am = fmaxf(am, __shfl_xor_sync(0xffffffffu, am, off));
            if ((tid & 31) == 0) atomicMax(maxw, __float_as_uint(am));
            __syncthreads();

            if (tid == 0) {
                g_maxarr[nxt][blockIdx.x] = __uint_as_float(*maxw);
                gbar_arrive_spin(++genl);
            }
            __syncthreads();
            __threadfence();

            float mx = 0.0f;
#pragma unroll
            for (int b = 0; b < LOGZ_BLOCKS; b++) mx = fmaxf(mx, __ldcg(&g_maxarr[nxt][b]));
            float scale = fmaxf(mx, 1e-30f);
            log_scale += logf(scale);
            inv_scale = 1.0f / scale;
        }

        if (blockIdx.x == 0) {
            float part = 0.0f;
            if (tid < 128) {
                int k = tid & 63, p = tid >> 6;
                float s = 0.0f;
#pragma unroll 8
                for (int e = 0; e < 64; e++)
                    s = fmaf(__ldcg(&g_envbuf[0][k * 64 + e]), right[e * 2 + p], s);
                part = right[k * 2 + p] * s;
            }
            smem[LZ_RED + tid] = part;
            __syncthreads();
            for (int s = 128; s > 0; s >>= 1) {
                if (tid < s) smem[LZ_RED + tid] += smem[LZ_RED + tid + s];
                __syncthreads();
            }
            if (tid == 0) {
                g_logz = logf(fmaxf(smem[LZ_RED] * inv_scale, 1e-30f)) + log_scale;
                __threadfence();
                unsigned o = atomicAdd(&g_fin, 1u);
                if (o == PSI_BLOCKS) {
                    float s = 0.0f;
                    for (int i = 0; i < PSI_BLOCKS; i++) s += __ldcg(&g_blocksums[i]);
                    out[0] = g_logz - s * (1.0f / (float)NBATCH);
                    __threadfence();
                    g_fin = 0;
                    __threadfence();
                }
            }
        }

        __syncthreads();
        if (tid == 0) {
            unsigned dn = atomicAdd(&g_done, 1u);
            if (dn == LOGZ_BLOCKS - 1) {
                g_done = 0;
                g_bar_gen = 0;
                __threadfence();
            }
        }
        return;
    }

    // ======= psi path: 256 blocks x 32 samples, mma.sync tf32, 2 blocks/SM ===
    const int bi = blockIdx.x - LOGZ_BLOCKS;
    const int m0 = bi * MBLK;
    const int lane = tid & 31;
    const int w = tid >> 5;
    const int g = lane >> 2, tq = lane & 3;
    const int mtile = w & 1;          // rows 16*mtile .. +15
    const int nq = w >> 1;            // n quarter: 32 n's, n base = nq*32
    const int h = nq >> 1;            // phys branch of this warp's n range
    const int r0 = mtile * 16 + g, r1 = r0 + 8;
    unsigned char* cfgS = (unsigned char*)(smem + SM_CFG);
    const unsigned smemB_base = (unsigned)__cvta_generic_to_shared(smem + SM_B);

    // prefetch B(site0): 4096 float4 / 256 thr
    {
        const float4* src = (const float4*)g_bulkT;
#pragma unroll
        for (int i = 0; i < 16; i++)
            cp16(smemB_base + (unsigned)(tid + (i << 8)) * 16u, src + tid + (i << 8));
        cp_commit();
    }

    // stage cfg + right
    for (int idx = tid; idx < 64 * MBLK; idx += NTHREADS) {
        int mm = idx & 31, s = idx >> 5;
        cfgS[s * MBLK + mm] = (unsigned char)cfg[(size_t)(m0 + mm) * 64 + s];
    }
    if (tid < 128) smem[SM_RIGHT + tid] = right[tid];
    __syncthreads();

    // env0[m][k] = left[cfg0(m)][k]
    for (int idx = tid; idx < MBLK * 64; idx += NTHREADS) {
        int k = idx >> 5, mm = idx & 31;
        smem[SM_ENV + mm * ENV_STRIDE + k] = left[(int)cfgS[mm] * 64 + k];
    }

    float ps0 = 0.0f, ps1 = 0.0f;

    for (int t = 0; t < NBULK; t++) {
        cp_wait0();
        __syncthreads();   // B[t] resident; env stores from t-1 visible

        // ---- A fragments (env rows r0, r1), hi/lo tf32 split ----
        unsigned ah[8][4], al[8][4];
#pragma unroll
        for (int kt = 0; kt < 8; kt++) {
            const int c0 = kt * 8 + tq;
            float v0 = smem[SM_ENV + r0 * ENV_STRIDE + c0];
            float v1 = smem[SM_ENV + r1 * ENV_STRIDE + c0];
            float v2 = smem[SM_ENV + r0 * ENV_STRIDE + c0 + 4];
            float v3 = smem[SM_ENV + r1 * ENV_STRIDE + c0 + 4];
            unsigned h0 = __float_as_uint(v0) & 0xFFFFE000u;
            unsigned h1 = __float_as_uint(v1) & 0xFFFFE000u;
            unsigned h2 = __float_as_uint(v2) & 0xFFFFE000u;
            unsigned h3 = __float_as_uint(v3) & 0xFFFFE000u;
            ah[kt][0] = h0; ah[kt][1] = h1; ah[kt][2] = h2; ah[kt][3] = h3;
            al[kt][0] = __float_as_uint(v0 - __uint_as_float(h0)) & 0xFFFFE000u;
            al[kt][1] = __float_as_uint(v1 - __uint_as_float(h1)) & 0xFFFFE000u;
            al[kt][2] = __float_as_uint(v2 - __uint_as_float(h2)) & 0xFFFFE000u;
            al[kt][3] = __float_as_uint(v3 - __uint_as_float(h3)) & 0xFFFFE000u;
        }

        // ---- MMA: D[32m x 128n], this warp: 16m x 32n, 3xTF32 ----
        const float4* Bh4 = (const float4*)(smem + SM_B);
        const float4* Bl4 = Bh4 + 2048;

        float d[4][4];
#pragma unroll
        for (int i = 0; i < 4; i++) { d[i][0] = 0.f; d[i][1] = 0.f; d[i][2] = 0.f; d[i][3] = 0.f; }

#pragma unroll
        for (int kt = 0; kt < 8; kt++) {
            float4 bh0 = Bh4[kt * 256 + (2 * nq + 0) * 32 + lane];
            float4 bh1 = Bh4[kt * 256 + (2 * nq + 1) * 32 + lane];
            float4 bl0 = Bl4[kt * 256 + (2 * nq + 0) * 32 + lane];
            float4 bl1 = Bl4[kt * 256 + (2 * nq + 1) * 32 + lane];
#pragma unroll
            for (int ntl = 0; ntl < 4; ntl++) {
                const float4& bh = (ntl >> 1) ? bh1 : bh0;
                unsigned b0 = __float_as_uint((ntl & 1) ? bh.z : bh.x);
                unsigned b1 = __float_as_uint((ntl & 1) ? bh.w : bh.y);
                mma8(d[ntl][0], d[ntl][1], d[ntl][2], d[ntl][3],
                     ah[kt][0], ah[kt][1], ah[kt][2], ah[kt][3], b0, b1);
                mma8(d[ntl][0], d[ntl][1], d[ntl][2], d[ntl][3],
                     al[kt][0], al[kt][1], al[kt][2], al[kt][3], b0, b1);
                const float4& bl = (ntl >> 1) ? bl1 : bl0;
                unsigned c0 = __float_as_uint((ntl & 1) ? bl.z : bl.x);
                unsigned c1 = __float_as_uint((ntl & 1) ? bl.w : bl.y);
                mma8(d[ntl][0], d[ntl][1], d[ntl][2], d[ntl][3],
                     ah[kt][0], ah[kt][1], ah[kt][2], ah[kt][3], c0, c1);
            }
        }
        __syncthreads();   // all B[t] reads + env reads done

        // overwrite B with next site while epilogue runs
        if (t + 1 < NBULK) {
            const float4* src = (const float4*)(g_bulkT + (size_t)(t + 1) * 16384);
#pragma unroll
            for (int i = 0; i < 16; i++)
                cp16(smemB_base + (unsigned)(tid + (i << 8)) * 16u, src + tid + (i << 8));
            cp_commit();
        }

        // ---- epilogue: predicated select/store ----
        if (t < NBULK - 1) {
            const int sel0 = cfgS[(t + 1) * MBLK + r0];
            const int sel1 = cfgS[(t + 1) * MBLK + r1];
#pragma unroll
            for (int ntl = 0; ntl < 4; ntl++) {
                const int j0 = (nq & 1) * 32 + ntl * 8 + 2 * tq;
                if (sel0 == h)
                    *(float2*)&smem[SM_ENV + r0 * ENV_STRIDE + j0] = make_float2(d[ntl][0], d[ntl][1]);
                if (sel1 == h)
                    *(float2*)&smem[SM_ENV + r1 * ENV_STRIDE + j0] = make_float2(d[ntl][2], d[ntl][3]);
            }
        } else {
            const int sel0 = cfgS[62 * MBLK + r0], sl0 = cfgS[63 * MBLK + r0];
            const int sel1 = cfgS[62 * MBLK + r1], sl1 = cfgS[63 * MBLK + r1];
#pragma unroll
            for (int ntl = 0; ntl < 4; ntl++) {
                const int j0 = (nq & 1) * 32 + ntl * 8 + 2 * tq;
                if (sel0 == h) {
                    ps0 = fmaf(d[ntl][0], smem[SM_RIGHT + j0 * 2 + sl0], ps0);
                    ps0 = fmaf(d[ntl][1], smem[SM_RIGHT + (j0 + 1) * 2 + sl0], ps0);
                }
                if (sel1 == h) {
                    ps1 = fmaf(d[ntl][2], smem[SM_RIGHT + j0 * 2 + sl1], ps1);
                    ps1 = fmaf(d[ntl][3], smem[SM_RIGHT + (j0 + 1) * 2 + sl1], ps1);
                }
            }
        }
    }

    // reduce psi partials within warp (tq lanes), then across nq quarters
    ps0 += __shfl_xor_sync(0xffffffffu, ps0, 1);
    ps0 += __shfl_xor_sync(0xffffffffu, ps0, 2);
    ps1 += __shfl_xor_sync(0xffffffffu, ps1, 1);
    ps1 += __shfl_xor_sync(0xffffffffu, ps1, 2);
    __syncthreads();
    if (tq == 0) {
        smem[SM_RED + nq * 32 + r0] = ps0;
        smem[SM_RED + nq * 32 + r1] = ps1;
    }
    __syncthreads();
    if (tid < 32) {
        float psi = smem[SM_RED + tid] + smem[SM_RED + 32 + tid]
                  + smem[SM_RED + 64 + tid] + smem[SM_RED + 96 + tid];
        smem[SM_RED + tid] = logf(fmaxf(psi * psi, 1e-12f));
    }
    __syncthreads();
    if (tid == 0) {
        float s = 0.0f;
#pragma unroll 8
        for (int i = 0; i < 32; i++) s += smem[SM_RED + i];
        g_blocksums[bi] = s;
        __threadfence();
        unsigned o = atomicAdd(&g_fin, 1u);
        if (o == PSI_BLOCKS) {   // last arrival overall (256 psi + 1 logz)
            float tot = 0.0f;
            for (int i = 0; i < PSI_BLOCKS; i++) tot += __ldcg(&g_blocksums[i]);
            out[0] = g_logz - tot * (1.0f / (float)NBATCH);
            __threadfence();
            g_fin = 0;
            __threadfence();
        }
    }
}

extern "C" void kernel_launch(void* const* d_in, const int* in_sizes, int n_in,
                              void* d_out, int out_size) {
    const int*   cfg   = (const int*)d_in[0];
    const float* left  = (const float*)d_in[1];
    const float* bulk  = (const float*)d_in[2];
    const float* right = (const float*)d_in[3];

    cudaFuncSetAttribute(main_kernel, cudaFuncAttributeMaxDynamicSharedMemorySize,
                         SM_TOTALF * 4);

    pre_kernel<<<NBULK, NTHREADS>>>(bulk);
    main_kernel<<<TOTAL_BLOCKS, NTHREADS, SM_TOTALF * 4>>>(cfg, left, bulk, right,
                                                           (float*)d_out);
}

// round 11
// speedup vs baseline: 1.0827x; 1.0827x over previous
#include <cuda_runtime.h>
#include <math.h>
#include <stdint.h>
#include <cstdint>

#define NBULK        62
#define DDIM         64
#define NBATCH       8192
#define PSI_BLOCKS   128
#define TOTAL_BLOCKS (1 + PSI_BLOCKS)
#define NTHREADS     512
#define MBLK         64

// ---------------- psi-block shared memory layout (float offsets) -------------
#define ENV_STRIDE 68
#define SM_ENV     0                        // 64*68 = 4352 (env[m][k])
#define SM_RIGHT   4352                     // 128
#define SM_RED     4480                     // 256 ([4 ng][64 m])
#define SM_CFG     4736                     // 1024 floats = 4096 B (cfgS[site][m])
#define SM_B       5760                     // byte 23040 (128B aligned); 2 x 16384
#define PSI_TOTALF (5760 + 2 * 16384)       // 38528 floats

// ---------------- logz-block shared memory layout ----------------------------
#define LZ_ENV   0                          // 64*68 = 4352 (env[i][j])
#define LZ_TMP   4352                       // 64*132 = 8448 (tmp[d][(p,j)])
#define LZ_B1    12800                      // 16384 (phase1 B hi|lo, frag order)
#define LZ_B2    29184                      // 16384 (phase2 B hi|lo, frag order)
#define LZ_RED   45568                      // 256 (maxw + z reduce)
#define LZ_TOTALF 45824

#define SM_TOTALF LZ_TOTALF                 // 183296 bytes

// ---------------- global scratch (zero-initialized at load) ------------------
__device__ float    g_bulkT [(size_t)NBULK * 16384];  // psi/logz-ph1 B frags hi|lo
__device__ float    g_bulkT2[(size_t)NBULK * 16384];  // logz-ph2 B frags hi|lo
__device__ float    g_blocksums[PSI_BLOCKS];
__device__ float    g_logz;
__device__ unsigned g_fin;

__device__ __forceinline__ void cp16(unsigned dst, const void* src) {
    asm volatile("cp.async.cg.shared.global [%0], [%1], 16;" :: "r"(dst), "l"(src) : "memory");
}
__device__ __forceinline__ void cp_commit() { asm volatile("cp.async.commit_group;" ::: "memory"); }
__device__ __forceinline__ void cp_wait0()  { asm volatile("cp.async.wait_group 0;" ::: "memory"); }

// m16n8k8 tf32 MMA, f32 accumulate in-place
__device__ __forceinline__ void mma8(float* d,
                                     unsigned a0, unsigned a1, unsigned a2, unsigned a3,
                                     unsigned b0, unsigned b1) {
    asm volatile("mma.sync.aligned.m16n8k8.row.col.f32.tf32.tf32.f32 "
                 "{%0,%1,%2,%3}, {%4,%5,%6,%7}, {%8,%9}, {%0,%1,%2,%3};"
                 : "+f"(d[0]), "+f"(d[1]), "+f"(d[2]), "+f"(d[3])
                 : "r"(a0), "r"(a1), "r"(a2), "r"(a3), "r"(b0), "r"(b1));
}

// ============ pre-pass: bake tf32 hi/lo fragment-order operands ==============
__global__ void pre_kernel(const float* __restrict__ bulk) {
    const int t = blockIdx.x;
    const float* src = bulk + (size_t)t * 8192;       // [d][n], n = p*64+j
    float* d1 = g_bulkT  + (size_t)t * 16384;
    float* d2 = g_bulkT2 + (size_t)t * 16384;
    // phase1 / psi B: element B[k][n] = src[k*128 + n]; K=64, N=128
    for (int idx = threadIdx.x; idx < 8192; idx += blockDim.x) {
        int k = idx >> 7, n = idx & 127;
        float v = src[idx];
        unsigned hb = __float_as_uint(v) & 0xFFFFE000u;
        float lof = v - __uint_as_float(hb);
        unsigned lb = __float_as_uint(lof) & 0xFFFFE000u;
        int kt   = k >> 3;
        int lane = ((n & 7) << 2) | (k & 3);
        int b    = (k >> 2) & 1;
        int ntp  = n >> 4;
        int q    = (((n >> 3) & 1) << 1) | b;
        int off  = kt * 1024 + ntp * 128 + lane * 4 + q;
        d1[off]        = __uint_as_float(hb);
        d1[8192 + off] = __uint_as_float(lb);
    }
    // phase2 B: element B2[K][i] = A_p[d][i] = src[d*128 + p*64 + i]; K=(p,d)=128, N=64
    for (int idx = threadIdx.x; idx < 8192; idx += blockDim.x) {
        int K = idx >> 6, n = idx & 63;
        float v = src[(K & 63) * 128 + (K >> 6) * 64 + n];
        unsigned hb = __float_as_uint(v) & 0xFFFFE000u;
        float lof = v - __uint_as_float(hb);
        unsigned lb = __float_as_uint(lof) & 0xFFFFE000u;
        int kt   = K >> 3;
        int lane = ((n & 7) << 2) | (K & 3);
        int b    = (K >> 2) & 1;
        int ntp  = n >> 4;
        int q    = (((n >> 3) & 1) << 1) | b;
        int off  = kt * 512 + ntp * 128 + lane * 4 + q;
        d2[off]        = __uint_as_float(hb);
        d2[8192 + off] = __uint_as_float(lb);
    }
}

__global__ __launch_bounds__(NTHREADS, 1)
void main_kernel(const int* __restrict__ cfg,
                 const float* __restrict__ left,
                 const float* __restrict__ bulk,
                 const float* __restrict__ right,
                 float* __restrict__ out) {
    extern __shared__ float smem[];
    const int tid = threadIdx.x;
    const int lane = tid & 31;
    const int w = tid >> 5;
    const int g = lane >> 2, tq = lane & 3;
    const unsigned smem_base = (unsigned)__cvta_generic_to_shared(smem);

    if (blockIdx.x == 0) {
        // ========== log-Z: ONE block, tensor cores, no global barriers ==========
        unsigned* maxw = (unsigned*)(smem + LZ_RED);
        const unsigned b1_addr = smem_base + LZ_B1 * 4;
        const unsigned b2_addr = smem_base + LZ_B2 * 4;

        // env0 = left^T @ left
        for (int idx = tid; idx < 4096; idx += NTHREADS) {
            int i = idx >> 6, j = idx & 63;
            smem[LZ_ENV + i * ENV_STRIDE + j] =
                left[i] * left[j] + left[64 + i] * left[64 + j];
        }
        // prefetch both B tiles for site 0 (4096 f4 each / 512 thr)
        {
            const float4* s1 = (const float4*)g_bulkT;
            const float4* s2 = (const float4*)g_bulkT2;
#pragma unroll
            for (int i = 0; i < 8; i++)
                cp16(b1_addr + (unsigned)(tid + (i << 9)) * 16u, s1 + tid + (i << 9));
#pragma unroll
            for (int i = 0; i < 8; i++)
                cp16(b2_addr + (unsigned)(tid + (i << 9)) * 16u, s2 + tid + (i << 9));
            cp_commit();
        }

        // phase1 warp tiles: mt = w&3 (16 rows d), nt = (w>>2)*4 + 0..3 (of 16)
        // phase2 warp tiles: mt (16 rows j), nt2 = (w>>2)*2 + 0..1 (of 8)
        const int mt = w & 3;
        const int ng = w >> 2;          // 0..3
        const int r0 = mt * 16 + g, r1 = r0 + 8;
        float log_scale = 0.0f;

        for (int t = 0; t < NBULK; t++) {
            cp_wait0();
            __syncthreads();            // B1,B2 resident; env ready

            // ---- phase1: tmp[d][(p,j)] = env @ [A0|A1], 3xTF32 ----
            {
                float dh[4][4], dl1[4][4], dl2[4][4];
#pragma unroll
                for (int i = 0; i < 4; i++)
#pragma unroll
                    for (int j = 0; j < 4; j++) { dh[i][j] = 0.f; dl1[i][j] = 0.f; dl2[i][j] = 0.f; }
                const float4* Bh4 = (const float4*)(smem + LZ_B1);
                const float4* Bl4 = Bh4 + 2048;
#pragma unroll
                for (int kt = 0; kt < 8; kt++) {
                    const int c0 = kt * 8 + tq;
                    float v0 = smem[LZ_ENV + r0 * ENV_STRIDE + c0];
                    float v1 = smem[LZ_ENV + r1 * ENV_STRIDE + c0];
                    float v2 = smem[LZ_ENV + r0 * ENV_STRIDE + c0 + 4];
                    float v3 = smem[LZ_ENV + r1 * ENV_STRIDE + c0 + 4];
                    unsigned h0 = __float_as_uint(v0) & 0xFFFFE000u;
                    unsigned h1 = __float_as_uint(v1) & 0xFFFFE000u;
                    unsigned h2 = __float_as_uint(v2) & 0xFFFFE000u;
                    unsigned h3 = __float_as_uint(v3) & 0xFFFFE000u;
                    unsigned l0 = __float_as_uint(v0 - __uint_as_float(h0)) & 0xFFFFE000u;
                    unsigned l1 = __float_as_uint(v1 - __uint_as_float(h1)) & 0xFFFFE000u;
                    unsigned l2 = __float_as_uint(v2 - __uint_as_float(h2)) & 0xFFFFE000u;
                    unsigned l3 = __float_as_uint(v3 - __uint_as_float(h3)) & 0xFFFFE000u;
                    float4 bh0 = Bh4[kt * 256 + (ng * 2 + 0) * 32 + lane];
                    float4 bh1 = Bh4[kt * 256 + (ng * 2 + 1) * 32 + lane];
                    float4 bl0 = Bl4[kt * 256 + (ng * 2 + 0) * 32 + lane];
                    float4 bl1 = Bl4[kt * 256 + (ng * 2 + 1) * 32 + lane];
#pragma unroll
                    for (int ntl = 0; ntl < 4; ntl++) {
                        const float4& bh = (ntl >> 1) ? bh1 : bh0;
                        const float4& bl = (ntl >> 1) ? bl1 : bl0;
                        unsigned b0 = __float_as_uint((ntl & 1) ? bh.z : bh.x);
                        unsigned b1 = __float_as_uint((ntl & 1) ? bh.w : bh.y);
                        unsigned c0b = __float_as_uint((ntl & 1) ? bl.z : bl.x);
                        unsigned c1b = __float_as_uint((ntl & 1) ? bl.w : bl.y);
                        mma8(dh[ntl],  h0, h1, h2, h3, b0, b1);
                        mma8(dl1[ntl], l0, l1, l2, l3, b0, b1);
                        mma8(dl2[ntl], h0, h1, h2, h3, c0b, c1b);
                    }
                }
                // store tmp
#pragma unroll
                for (int ntl = 0; ntl < 4; ntl++) {
                    const int j0 = (ng * 4 + ntl) * 8 + 2 * tq;
                    float s0 = dh[ntl][0] + dl1[ntl][0] + dl2[ntl][0];
                    float s1 = dh[ntl][1] + dl1[ntl][1] + dl2[ntl][1];
                    float s2 = dh[ntl][2] + dl1[ntl][2] + dl2[ntl][2];
                    float s3 = dh[ntl][3] + dl1[ntl][3] + dl2[ntl][3];
                    *(float2*)&smem[LZ_TMP + r0 * 132 + j0] = make_float2(s0, s1);
                    *(float2*)&smem[LZ_TMP + r1 * 132 + j0] = make_float2(s2, s3);
                }
            }
            if (tid == 0) *maxw = 0u;
            __syncthreads();            // tmp ready; maxw reset; B1 reads done

            // prefetch B1(t+1)
            if (t + 1 < NBULK) {
                const float4* s1 = (const float4*)(g_bulkT + (size_t)(t + 1) * 16384);
#pragma unroll
                for (int i = 0; i < 8; i++)
                    cp16(b1_addr + (unsigned)(tid + (i << 9)) * 16u, s1 + tid + (i << 9));
                cp_commit();
            }

            // ---- phase2: env'[j][i] = sum_{(p,d)} tmp[d][p*64+j] * A_p[d][i] ----
            float ds[2][4];
            {
                float dh[2][4], dl1[2][4], dl2[2][4];
#pragma unroll
                for (int i = 0; i < 2; i++)
#pragma unroll
                    for (int j = 0; j < 4; j++) { dh[i][j] = 0.f; dl1[i][j] = 0.f; dl2[i][j] = 0.f; }
                const float4* B2h4 = (const float4*)(smem + LZ_B2);
                const float4* B2l4 = B2h4 + 2048;
#pragma unroll
                for (int kt2 = 0; kt2 < 16; kt2++) {
                    const int K0 = kt2 * 8 + tq;
                    const int a0off = (K0 & 63) * 132 + (K0 >> 6) * 64;
                    const int a1off = ((K0 + 4) & 63) * 132 + ((K0 + 4) >> 6) * 64;
                    float v0 = smem[LZ_TMP + a0off + r0];
                    float v1 = smem[LZ_TMP + a0off + r1];
                    float v2 = smem[LZ_TMP + a1off + r0];
                    float v3 = smem[LZ_TMP + a1off + r1];
                    unsigned h0 = __float_as_uint(v0) & 0xFFFFE000u;
                    unsigned h1 = __float_as_uint(v1) & 0xFFFFE000u;
                    unsigned h2 = __float_as_uint(v2) & 0xFFFFE000u;
                    unsigned h3 = __float_as_uint(v3) & 0xFFFFE000u;
                    unsigned l0 = __float_as_uint(v0 - __uint_as_float(h0)) & 0xFFFFE000u;
                    unsigned l1 = __float_as_uint(v1 - __uint_as_float(h1)) & 0xFFFFE000u;
                    unsigned l2 = __float_as_uint(v2 - __uint_as_float(h2)) & 0xFFFFE000u;
                    unsigned l3 = __float_as_uint(v3 - __uint_as_float(h3)) & 0xFFFFE000u;
                    float4 bh = B2h4[kt2 * 128 + ng * 32 + lane];
                    float4 bl = B2l4[kt2 * 128 + ng * 32 + lane];
#pragma unroll
                    for (int ntl = 0; ntl < 2; ntl++) {
                        unsigned b0 = __float_as_uint(ntl ? bh.z : bh.x);
                        unsigned b1 = __float_as_uint(ntl ? bh.w : bh.y);
                        unsigned c0b = __float_as_uint(ntl ? bl.z : bl.x);
                        unsigned c1b = __float_as_uint(ntl ? bl.w : bl.y);
                        mma8(dh[ntl],  h0, h1, h2, h3, b0, b1);
                        mma8(dl1[ntl], l0, l1, l2, l3, b0, b1);
                        mma8(dl2[ntl], h0, h1, h2, h3, c0b, c1b);
                    }
                }
                float am = 0.0f;
#pragma unroll
                for (int ntl = 0; ntl < 2; ntl++)
#pragma unroll
                    for (int j = 0; j < 4; j++) {
                        ds[ntl][j] = dh[ntl][j] + dl1[ntl][j] + dl2[ntl][j];
                        am = fmaxf(am, fabsf(ds[ntl][j]));
                    }
#pragma unroll
                for (int off = 16; off > 0; off >>= 1)
                    am = fmaxf(am, __shfl_xor_sync(0xffffffffu, am, off));
                if (lane == 0) atomicMax(maxw, __float_as_uint(am));
            }
            __syncthreads();            // max ready; tmp+B2 reads done

            // prefetch B2(t+1)
            if (t + 1 < NBULK) {
                const float4* s2 = (const float4*)(g_bulkT2 + (size_t)(t + 1) * 16384);
#pragma unroll
                for (int i = 0; i < 8; i++)
                    cp16(b2_addr + (unsigned)(tid + (i << 9)) * 16u, s2 + tid + (i << 9));
                cp_commit();
            }

            const float scale = fmaxf(__uint_as_float(*maxw), 1e-30f);
            log_scale += logf(scale);
            const float inv = 1.0f / scale;
#pragma unroll
            for (int ntl = 0; ntl < 2; ntl++) {
                const int i0 = (ng * 2 + ntl) * 8 + 2 * tq;
                *(float2*)&smem[LZ_ENV + r0 * ENV_STRIDE + i0] =
                    make_float2(ds[ntl][0] * inv, ds[ntl][1] * inv);
                *(float2*)&smem[LZ_ENV + r1 * ENV_STRIDE + i0] =
                    make_float2(ds[ntl][2] * inv, ds[ntl][3] * inv);
            }
        }
        __syncthreads();

        // z = sum(right * (env @ right))
        float part = 0.0f;
        if (tid < 128) {
            int k = tid & 63, pp = tid >> 6;
            float s = 0.0f;
#pragma unroll 8
            for (int e = 0; e < 64; e++)
                s = fmaf(smem[LZ_ENV + k * ENV_STRIDE + e], right[e * 2 + pp], s);
            part = right[k * 2 + pp] * s;
        }
        if (tid < 128) smem[LZ_RED + 32 + tid] = part;
        __syncthreads();
        if (tid == 0) {
            float z = 0.0f;
            for (int i = 0; i < 128; i++) z += smem[LZ_RED + 32 + i];
            g_logz = logf(fmaxf(z, 1e-30f)) + log_scale;
            __threadfence();
            unsigned o = atomicAdd(&g_fin, 1u);
            if (o == PSI_BLOCKS) {
                float s = 0.0f;
                for (int i = 0; i < PSI_BLOCKS; i++) s += __ldcg(&g_blocksums[i]);
                out[0] = g_logz - s * (1.0f / (float)NBATCH);
                __threadfence();
                g_fin = 0;
                __threadfence();
            }
        }
        return;
    }

    // ======= psi: 128 blocks x 64 samples, 512 thr, 3-bank mma.sync tf32 ======
    const int bi = blockIdx.x - 1;
    const int m0 = bi * MBLK;
    const int mt = w & 3;           // m tile: rows 16mt..+15
    const int ng = w >> 2;          // 0..3: ntiles ng*4..+3 (n = 32ng..+31)
    const int h = ng >> 1;          // phys branch of this warp's n range
    const int r0 = mt * 16 + g, r1 = r0 + 8;
    unsigned char* cfgS = (unsigned char*)(smem + SM_CFG);
    const unsigned smemB_base = smem_base + SM_B * 4;

    // prefetch B(site0) buf0: 4096 f4 / 512 thr
    {
        const float4* src = (const float4*)g_bulkT;
#pragma unroll
        for (int i = 0; i < 8; i++)
            cp16(smemB_base + (unsigned)(tid + (i << 9)) * 16u, src + tid + (i << 9));
        cp_commit();
    }

    for (int idx = tid; idx < 64 * MBLK; idx += NTHREADS) {
        int mm = idx >> 6, s = idx & 63;
        cfgS[s * MBLK + mm] = (unsigned char)cfg[(size_t)(m0 + mm) * 64 + s];
    }
    if (tid < 128) smem[SM_RIGHT + tid] = right[tid];
    __syncthreads();

    for (int idx = tid; idx < 64 * 64; idx += NTHREADS) {
        int k = idx >> 6, mm = idx & 63;
        smem[SM_ENV + mm * ENV_STRIDE + k] = left[(int)cfgS[mm] * 64 + k];
    }

    float ps0 = 0.0f, ps1 = 0.0f;

    for (int t = 0; t < NBULK; t++) {
        cp_wait0();
        __syncthreads();

        if (t + 1 < NBULK) {
            const float4* src = (const float4*)(g_bulkT + (size_t)(t + 1) * 16384);
            unsigned dst = smemB_base + (unsigned)(((t + 1) & 1) * 65536u);
#pragma unroll
            for (int i = 0; i < 8; i++)
                cp16(dst + (unsigned)(tid + (i << 9)) * 16u, src + tid + (i << 9));
            cp_commit();
        }

        const float4* Bh4 = (const float4*)(smem + SM_B + (t & 1) * 16384);
        const float4* Bl4 = Bh4 + 2048;

        float dh[4][4], dl1[4][4], dl2[4][4];
#pragma unroll
        for (int i = 0; i < 4; i++)
#pragma unroll
            for (int j = 0; j < 4; j++) { dh[i][j] = 0.f; dl1[i][j] = 0.f; dl2[i][j] = 0.f; }

#pragma unroll
        for (int kt = 0; kt < 8; kt++) {
            const int c0 = kt * 8 + tq;
            float v0 = smem[SM_ENV + r0 * ENV_STRIDE + c0];
            float v1 = smem[SM_ENV + r1 * ENV_STRIDE + c0];
            float v2 = smem[SM_ENV + r0 * ENV_STRIDE + c0 + 4];
            float v3 = smem[SM_ENV + r1 * ENV_STRIDE + c0 + 4];
            unsigned h0 = __float_as_uint(v0) & 0xFFFFE000u;
            unsigned h1 = __float_as_uint(v1) & 0xFFFFE000u;
            unsigned h2 = __float_as_uint(v2) & 0xFFFFE000u;
            unsigned h3 = __float_as_uint(v3) & 0xFFFFE000u;
            unsigned l0 = __float_as_uint(v0 - __uint_as_float(h0)) & 0xFFFFE000u;
            unsigned l1 = __float_as_uint(v1 - __uint_as_float(h1)) & 0xFFFFE000u;
            unsigned l2 = __float_as_uint(v2 - __uint_as_float(h2)) & 0xFFFFE000u;
            unsigned l3 = __float_as_uint(v3 - __uint_as_float(h3)) & 0xFFFFE000u;
            float4 bh0 = Bh4[kt * 256 + (ng * 2 + 0) * 32 + lane];
            float4 bh1 = Bh4[kt * 256 + (ng * 2 + 1) * 32 + lane];
            float4 bl0 = Bl4[kt * 256 + (ng * 2 + 0) * 32 + lane];
            float4 bl1 = Bl4[kt * 256 + (ng * 2 + 1) * 32 + lane];
#pragma unroll
            for (int ntl = 0; ntl < 4; ntl++) {
                const float4& bh = (ntl >> 1) ? bh1 : bh0;
                const float4& bl = (ntl >> 1) ? bl1 : bl0;
                unsigned b0 = __float_as_uint((ntl & 1) ? bh.z : bh.x);
                unsigned b1 = __float_as_uint((ntl & 1) ? bh.w : bh.y);
                unsigned c0b = __float_as_uint((ntl & 1) ? bl.z : bl.x);
                unsigned c1b = __float_as_uint((ntl & 1) ? bl.w : bl.y);
                mma8(dh[ntl],  h0, h1, h2, h3, b0, b1);
                mma8(dl1[ntl], l0, l1, l2, l3, b0, b1);
                mma8(dl2[ntl], h0, h1, h2, h3, c0b, c1b);
            }
        }
        __syncthreads();   // env + B reads done

        if (t < NBULK - 1) {
            const int sel0 = cfgS[(t + 1) * MBLK + r0];
            const int sel1 = cfgS[(t + 1) * MBLK + r1];
#pragma unroll
            for (int ntl = 0; ntl < 4; ntl++) {
                const int j0 = (ng & 1) * 32 + ntl * 8 + 2 * tq;
                if (sel0 == h)
                    *(float2*)&smem[SM_ENV + r0 * ENV_STRIDE + j0] =
                        make_float2(dh[ntl][0] + dl1[ntl][0] + dl2[ntl][0],
                                    dh[ntl][1] + dl1[ntl][1] + dl2[ntl][1]);
                if (sel1 == h)
                    *(float2*)&smem[SM_ENV + r1 * ENV_STRIDE + j0] =
                        make_float2(dh[ntl][2] + dl1[ntl][2] + dl2[ntl][2],
                                    dh[ntl][3] + dl1[ntl][3] + dl2[ntl][3]);
            }
        } else {
            const int sel0 = cfgS[62 * MBLK + r0], sl0 = cfgS[63 * MBLK + r0];
            const int sel1 = cfgS[62 * MBLK + r1], sl1 = cfgS[63 * MBLK + r1];
#pragma unroll
            for (int ntl = 0; ntl < 4; ntl++) {
                const int j0 = (ng & 1) * 32 + ntl * 8 + 2 * tq;
                if (sel0 == h) {
                    float a = dh[ntl][0] + dl1[ntl][0] + dl2[ntl][0];
                    float b = dh[ntl][1] + dl1[ntl][1] + dl2[ntl][1];
                    ps0 = fmaf(a, smem[SM_RIGHT + j0 * 2 + sl0], ps0);
                    ps0 = fmaf(b, smem[SM_RIGHT + (j0 + 1) * 2 + sl0], ps0);
                }
                if (sel1 == h) {
                    float a = dh[ntl][2] + dl1[ntl][2] + dl2[ntl][2];
                    float b = dh[ntl][3] + dl1[ntl][3] + dl2[ntl][3];
                    ps1 = fmaf(a, smem[SM_RIGHT + j0 * 2 + sl1], ps1);
                    ps1 = fmaf(b, smem[SM_RIGHT + (j0 + 1) * 2 + sl1], ps1);
                }
            }
        }
    }

    // reduce psi partials: lanes sharing a row differ in tq; then across ng
    ps0 += __shfl_xor_sync(0xffffffffu, ps0, 1);
    ps0 += __shfl_xor_sync(0xffffffffu, ps0, 2);
    ps1 += __shfl_xor_sync(0xffffffffu, ps1, 1);
    ps1 += __shfl_xor_sync(0xffffffffu, ps1, 2);
    __syncthreads();
    if (tq == 0) {
        smem[SM_RED + ng * 64 + r0] = ps0;
        smem[SM_RED + ng * 64 + r1] = ps1;
    }
    __syncthreads();
    if (tid < 64) {
        float psi = smem[SM_RED + tid] + smem[SM_RED + 64 + tid]
                  + smem[SM_RED + 128 + tid] + smem[SM_RED + 192 + tid];
        smem[SM_RED + tid] = logf(fmaxf(psi * psi, 1e-12f));
    }
    __syncthreads();
    if (tid == 0) {
        float s = 0.0f;
#pragma unroll 8
        for (int i = 0; i < 64; i++) s += smem[SM_RED + i];
        g_blocksums[bi] = s;
        __threadfence();
        unsigned o = atomicAdd(&g_fin, 1u);
        if (o == PSI_BLOCKS) {
            float tot = 0.0f;
            for (int i = 0; i < PSI_BLOCKS; i++) tot += __ldcg(&g_blocksums[i]);
            out[0] = g_logz - tot * (1.0f / (float)NBATCH);
            __threadfence();
            g_fin = 0;
            __threadfence();
        }
    }
}

extern "C" void kernel_launch(void* const* d_in, const int* in_sizes, int n_in,
                              void* d_out, int out_size) {
    const int*   cfg   = (const int*)d_in[0];
    const float* left  = (const float*)d_in[1];
    const float* bulk  = (const float*)d_in[2];
    const float* right = (const float*)d_in[3];

    cudaFuncSetAttribute(main_kernel, cudaFuncAttributeMaxDynamicSharedMemorySize,
                         SM_TOTALF * 4);

    pre_kernel<<<NBULK, 256>>>(bulk);
    main_kernel<<<TOTAL_BLOCKS, NTHREADS, SM_TOTALF * 4>>>(cfg, left, bulk, right,
                                                           (float*)d_out);
}